// round 2
// baseline (speedup 1.0000x reference)
#include <cuda_runtime.h>
#include <cstdint>

// ViT patch embedding: out[128,197,768]
//   rows 1..196 per image: patchify(images) @ W^T + b
//   row 0 per image: cls_token
//
// GEMM: M=25088 (128 img * 196 patches), N=768, K=768
// A[m,k] gathered from images: m=img*196+patch, patch=Pi*14+Pj,
//   k=c*256+ph*16+pw  ->  images[img, c, Pi*16+ph, Pj*16+pw]

#define P_CNT   14
#define NPATCH  196
#define NIMG    128
#define KDIM    768
#define NDIM    768
#define MTOT    (NIMG * NPATCH)   // 25088

#define BM 128
#define BN 128
#define BK 16
#define KST 20                     // padded smem stride (conflict-free: 20g+tg perm mod 32)
#define NITER (KDIM / BK)          // 48

__device__ __forceinline__ uint32_t f2tf(float x) {
    uint32_t r;
    asm("cvt.rna.tf32.f32 %0, %1;" : "=r"(r) : "f"(x));
    return r;
}

__device__ __forceinline__ void mma_tf32(float* c, const uint32_t* a, const uint32_t* b) {
    asm volatile(
        "mma.sync.aligned.m16n8k8.row.col.f32.tf32.tf32.f32 "
        "{%0,%1,%2,%3}, {%4,%5,%6,%7}, {%8,%9}, {%0,%1,%2,%3};\n"
        : "+f"(c[0]), "+f"(c[1]), "+f"(c[2]), "+f"(c[3])
        : "r"(a[0]), "r"(a[1]), "r"(a[2]), "r"(a[3]), "r"(b[0]), "r"(b[1]));
}

__device__ __forceinline__ void cp16(uint32_t s, const void* g) {
    asm volatile("cp.async.cg.shared.global [%0], [%1], 16;\n" :: "r"(s), "l"(g));
}
__device__ __forceinline__ void cp_commit() {
    asm volatile("cp.async.commit_group;\n");
}
template <int N>
__device__ __forceinline__ void cp_wait() {
    asm volatile("cp.async.wait_group %0;\n" :: "n"(N));
}

__global__ __launch_bounds__(256) void vit_gemm_kernel(
    const float* __restrict__ images,
    const float* __restrict__ W,       // [768 out, 768 in] row-major
    const float* __restrict__ bias,    // [768]
    float* __restrict__ out)           // [128, 197, 768]
{
    __shared__ __align__(16) float As[2][BM][KST];
    __shared__ __align__(16) float Bs[2][BM][KST];

    const int tid  = threadIdx.x;
    const int lane = tid & 31;
    const int warp = tid >> 5;
    const int wm   = warp >> 1;   // 0..3  -> 32 rows each
    const int wn   = warp & 1;    // 0..1  -> 64 cols each
    const int g    = lane >> 2;   // 0..7
    const int tg   = lane & 3;    // 0..3

    const int bm = blockIdx.y * BM;
    const int bn = blockIdx.x * BN;

    // ---- loader mapping: 512 float4 per tile, 2 per thread ----
    const int lr = tid >> 2;      // 0..63 (row within tile; also +64)
    const int lq = tid & 3;       // quad within 16-float segment
    const int pw = lq * 4;

    // A source base (per fixed row), k-dependent offset added per iter
    long abase[2];
    #pragma unroll
    for (int i = 0; i < 2; ++i) {
        int m     = bm + lr + i * 64;          // always < 25088
        int img   = m / NPATCH;
        int patch = m % NPATCH;
        int Pi    = patch / P_CNT;
        int Pj    = patch % P_CNT;
        abase[i] = ((long)(img * 3) * 224 + Pi * 16) * 224 + Pj * 16 + pw;
    }
    const float* bsrc0 = W + (long)(bn + lr) * KDIM + pw;
    const float* bsrc1 = W + (long)(bn + lr + 64) * KDIM + pw;

    const uint32_t sA = (uint32_t)__cvta_generic_to_shared(&As[0][0][0]);
    const uint32_t sB = (uint32_t)__cvta_generic_to_shared(&Bs[0][0][0]);
    const uint32_t bufBytes = BM * KST * 4;
    const uint32_t dA0 = (uint32_t)(lr * KST + pw) * 4;
    const uint32_t dA1 = (uint32_t)((lr + 64) * KST + pw) * 4;

    auto load_tile = [&](int buf, int it) {
        const int  k0 = it * BK;
        const int  c  = k0 >> 8;             // channel (0..2)
        const int  ph = (k0 >> 4) & 15;      // row within patch
        const long ko = (long)c * (224 * 224) + (long)ph * 224;
        cp16(sA + buf * bufBytes + dA0, images + abase[0] + ko);
        cp16(sA + buf * bufBytes + dA1, images + abase[1] + ko);
        cp16(sB + buf * bufBytes + dA0, bsrc0 + k0);
        cp16(sB + buf * bufBytes + dA1, bsrc1 + k0);
    };

    float acc[2][8][4];
    #pragma unroll
    for (int mt = 0; mt < 2; ++mt)
        #pragma unroll
        for (int nt = 0; nt < 8; ++nt)
            #pragma unroll
            for (int r = 0; r < 4; ++r) acc[mt][nt][r] = 0.f;

    load_tile(0, 0);
    cp_commit();

    for (int it = 0; it < NITER; ++it) {
        const int buf = it & 1;
        if (it + 1 < NITER) {
            load_tile(buf ^ 1, it + 1);
            cp_commit();
            cp_wait<1>();
        } else {
            cp_wait<0>();
        }
        __syncthreads();

        #pragma unroll
        for (int ks = 0; ks < 2; ++ks) {
            const int kb = ks * 8;
            uint32_t af[2][4], bf[8][2];
            #pragma unroll
            for (int mt = 0; mt < 2; ++mt) {
                const int row = wm * 32 + mt * 16;
                af[mt][0] = f2tf(As[buf][row + g][kb + tg]);
                af[mt][1] = f2tf(As[buf][row + g + 8][kb + tg]);
                af[mt][2] = f2tf(As[buf][row + g][kb + tg + 4]);
                af[mt][3] = f2tf(As[buf][row + g + 8][kb + tg + 4]);
            }
            #pragma unroll
            for (int nt = 0; nt < 8; ++nt) {
                const int col = wn * 64 + nt * 8;
                bf[nt][0] = f2tf(Bs[buf][col + g][kb + tg]);
                bf[nt][1] = f2tf(Bs[buf][col + g][kb + tg + 4]);
            }
            #pragma unroll
            for (int mt = 0; mt < 2; ++mt)
                #pragma unroll
                for (int nt = 0; nt < 8; ++nt)
                    mma_tf32(acc[mt][nt], af[mt], bf[nt]);
        }
        __syncthreads();
    }

    // ---- epilogue: bias + scatter to [img, 1+patch, n] ----
    float bv[8][2];
    #pragma unroll
    for (int nt = 0; nt < 8; ++nt) {
        const int col = bn + wn * 64 + nt * 8 + tg * 2;
        bv[nt][0] = bias[col];
        bv[nt][1] = bias[col + 1];
    }

    #pragma unroll
    for (int mt = 0; mt < 2; ++mt) {
        #pragma unroll
        for (int rh = 0; rh < 2; ++rh) {
            const int m     = bm + wm * 32 + mt * 16 + rh * 8 + g;
            const int img   = m / NPATCH;
            const int patch = m % NPATCH;
            float* orow = out + ((size_t)img * 197 + patch + 1) * NDIM;
            #pragma unroll
            for (int nt = 0; nt < 8; ++nt) {
                const int col = bn + wn * 64 + nt * 8 + tg * 2;
                float2 v;
                v.x = acc[mt][nt][rh * 2 + 0] + bv[nt][0];
                v.y = acc[mt][nt][rh * 2 + 1] + bv[nt][1];
                *reinterpret_cast<float2*>(orow + col) = v;
            }
        }
    }
}

__global__ void cls_kernel(const float* __restrict__ cls, float* __restrict__ out) {
    const int i = blockIdx.x * blockDim.x + threadIdx.x;   // 128*768
    if (i >= NIMG * NDIM) return;
    const int img = i / NDIM;
    const int n   = i % NDIM;
    out[(size_t)img * 197 * NDIM + n] = cls[n];
}

extern "C" void kernel_launch(void* const* d_in, const int* in_sizes, int n_in,
                              void* d_out, int out_size) {
    const float* images = (const float*)d_in[0];
    const float* W      = (const float*)d_in[1];
    const float* b      = (const float*)d_in[2];
    const float* cls    = (const float*)d_in[3];
    float* out          = (float*)d_out;

    dim3 grid(NDIM / BN, MTOT / BM);   // (6, 196): n fastest -> A-tile L2 reuse
    vit_gemm_kernel<<<grid, 256>>>(images, W, b, out);
    cls_kernel<<<(NIMG * NDIM + 255) / 256, 256>>>(cls, out);
}